// round 6
// baseline (speedup 1.0000x reference)
#include <cuda_runtime.h>
#include <cstdint>

#define N_BITS 108
#define N_OUT  7
#define TPB    256

// Row = 108 floats = 432 B = 27 uint4. DRAM effective granule = 64 B.
// Each lane scans its row through a 64B-ALIGNED window starting at
// A = row_start & ~63 (uint4 index a0 = (27*row) & ~3). The first
// d = 4*((27*row)&3) words of the window belong to the previous row and are
// masked off. Every round covers whole aligned granules -> no split waste.
// Values are exactly 0.0f / 1.0f: (word >> 29) & 1 extracts the bit.
// Window rounds (words): [0,16) [16,32) [32,64) [64,112) [112,128)-rare.

__device__ __forceinline__ unsigned mask4(uint4 w, int sh) {
    return (((w.x >> 29) & 1u) << sh)
         | (((w.y >> 29) & 1u) << (sh + 1))
         | (((w.z >> 29) & 1u) << (sh + 2))
         | (((w.w >> 29) & 1u) << (sh + 3));
}

__global__ __launch_bounds__(TPB, 8)
void lzd108_kernel(const uint4* __restrict__ X, float* __restrict__ out,
                   int n_rows, unsigned lim /* total uint4 count */) {
    __shared__ float s[TPB * N_OUT];

    int row = blockIdx.x * TPB + threadIdx.x;
    int pos = N_BITS;  // 108 = 1101100b == LZC_108 sentinel (all-zero row)

    if (row < n_rows) {
        unsigned w0 = 27u * (unsigned)row;   // uint4 index of row start
        unsigned a0 = w0 & ~3u;              // 64B-aligned window base (uint4)
        int d = 4 * (int)(w0 & 3u);          // junk words at window start {0,4,8,12}
        const uint4* p = X + a0;

        int pw = -1;  // first-one position in WINDOW coords; row pos = pw - d

        // Round 0: window words [0,16) — one aligned 64B granule
        unsigned m0 = 0;
        #pragma unroll
        for (int j = 0; j < 4; ++j) m0 |= mask4(__ldcs(p + j), 4 * j);
        m0 &= 0xFFFFu << d;                  // drop previous-row junk bits
        if (m0) {
            pw = __ffs(m0) - 1;
        } else {
            // Round 1: words [16,32) — 1 granule
            unsigned m1 = 0;
            #pragma unroll
            for (int j = 0; j < 4; ++j) m1 |= mask4(__ldcs(p + 4 + j), 4 * j);
            if (m1) {
                pw = 16 + __ffs(m1) - 1;
            } else {
                // Round 2: words [32,64) — 2 granules
                unsigned m2 = 0;
                #pragma unroll
                for (int j = 0; j < 8; ++j) m2 |= mask4(__ldcs(p + 8 + j), 4 * j);
                if (m2) {
                    pw = 32 + __ffs(m2) - 1;
                } else {
                    // Round 3: words [64,112) — 3 granules (bounds-guarded)
                    unsigned long long m3 = 0;
                    #pragma unroll
                    for (int j = 0; j < 12; ++j) {
                        unsigned gi = a0 + 16 + j;
                        uint4 w = (gi < lim) ? __ldcs(X + gi)
                                             : make_uint4(0u, 0u, 0u, 0u);
                        m3 |= (unsigned long long)mask4(w, 0) << (4 * j);
                    }
                    // valid window words: i < 108 + d  ->  local bit < 44 + d
                    m3 &= (d == 0) ? ((1ull << 44) - 1) : ((1ull << 48) - 1);
                    if (m3) {
                        pw = 64 + __ffsll(m3) - 1;
                    } else if (d >= 8) {
                        // Round 4: words [112,128) — row words 104..107 for d>=8
                        unsigned m4 = 0;
                        #pragma unroll
                        for (int j = 0; j < 4; ++j) {
                            unsigned gi = a0 + 28 + j;
                            uint4 w = (gi < lim) ? __ldcs(X + gi)
                                                 : make_uint4(0u, 0u, 0u, 0u);
                            m4 |= mask4(w, 4 * j);
                        }
                        m4 &= (1u << (d - 4)) - 1;   // d=8 -> 4 bits, d=12 -> 8
                        if (m4) pw = 112 + __ffs(m4) - 1;
                    }
                }
            }
        }
        if (pw >= 0) pos = pw - d;
    }

    // Stage outputs in smem (stride-7: gcd(7,32)=1 -> conflict-free), then
    // write the block's 1792 floats fully coalesced.
    #pragma unroll
    for (int j = 0; j < N_OUT; ++j)
        s[threadIdx.x * N_OUT + j] = (float)((pos >> (6 - j)) & 1);

    __syncthreads();

    size_t block_base = (size_t)blockIdx.x * (TPB * N_OUT);
    size_t total = (size_t)n_rows * N_OUT;
    #pragma unroll
    for (int i = 0; i < N_OUT; ++i) {
        size_t gi = block_base + i * TPB + threadIdx.x;
        if (gi < total) out[gi] = s[i * TPB + threadIdx.x];
    }
}

extern "C" void kernel_launch(void* const* d_in, const int* in_sizes, int n_in,
                              void* d_out, int out_size) {
    const uint4* X = (const uint4*)d_in[0];
    float* out = (float*)d_out;
    int n_rows = in_sizes[0] / N_BITS;
    unsigned lim = (unsigned)(in_sizes[0] / 4);  // total uint4 count

    int blocks = (n_rows + TPB - 1) / TPB;
    lzd108_kernel<<<blocks, TPB>>>(X, out, n_rows, lim);
}

// round 7
// speedup vs baseline: 1.4116x; 1.4116x over previous
#include <cuda_runtime.h>
#include <cstdint>

#define N_BITS 108
#define N_OUT  7
#define TPB    256
#define NWARPS (TPB / 32)

// Row = 108 floats = 432 B = 27 uint4. Values are exactly 0.0f / 1.0f:
// (word >> 29) & 1 extracts the bit.
// Phase 1 (row-per-thread, strided): rounds of 16/16/32 bits (words 0-3, 4-7,
// 8-15) with early exit. Phase 2 (warp-cooperative, coalesced): rows still
// unresolved (bits [0,64) all zero, ~14%) are queued in smem; warps drain the
// queue 2 rows/iter — lanes 0-10 and 16-26 each load one uint4 of words 16-26
// (one LDG instr covers 2x176B contiguous), ballot+shfl picks the first one.

__device__ __forceinline__ unsigned mask4(uint4 w) {
    return ((w.x >> 29) & 1u)
         | (((w.y >> 29) & 1u) << 1)
         | (((w.z >> 29) & 1u) << 2)
         | (((w.w >> 29) & 1u) << 3);
}

__global__ __launch_bounds__(TPB, 8)
void lzd108_kernel(const uint4* __restrict__ X, float* __restrict__ out, int n_rows) {
    __shared__ unsigned short s_pos[TPB];
    __shared__ unsigned short s_q[TPB];
    __shared__ int s_count;

    int tid = threadIdx.x;
    if (tid == 0) s_count = 0;
    __syncthreads();

    size_t brow = (size_t)blockIdx.x * TPB;
    int row = (int)brow + tid;
    int pos = N_BITS;  // 108 = 1101100b == LZC_108 (all-zero row)
    bool unresolved = false;

    if (row < n_rows) {
        const uint4* p = X + (size_t)row * 27;

        // Round 0: bits [0,16) — words 0..3
        unsigned m0 = 0;
        #pragma unroll
        for (int j = 0; j < 4; ++j) m0 |= mask4(p[j]) << (4 * j);
        if (m0) {
            pos = __ffs(m0) - 1;
        } else {
            // Round 1: bits [16,32) — words 4..7
            unsigned m1 = 0;
            #pragma unroll
            for (int j = 0; j < 4; ++j) m1 |= mask4(p[4 + j]) << (4 * j);
            if (m1) {
                pos = 16 + __ffs(m1) - 1;
            } else {
                // Round 2: bits [32,64) — words 8..15
                unsigned m2 = 0;
                #pragma unroll
                for (int j = 0; j < 8; ++j) m2 |= mask4(p[8 + j]) << (4 * j);
                if (m2) {
                    pos = 32 + __ffs(m2) - 1;
                } else {
                    unresolved = true;
                }
            }
        }
    }

    s_pos[tid] = (unsigned short)pos;
    if (unresolved) {
        int qi = atomicAdd(&s_count, 1);
        s_q[qi] = (unsigned short)tid;
    }
    __syncthreads();

    // Phase 2: cooperative tail scan (bits [64,108) = words 16..26).
    int nq = s_count;
    int lane = tid & 31;
    int wid = tid >> 5;

    for (int base = 2 * wid; base < nq; base += 2 * NWARPS) {
        int slot = base + (lane >> 4);   // lanes 0-15 -> base, 16-31 -> base+1
        int li = lane & 15;              // word index within the tail
        unsigned mymask = 0;
        if (li < 11 && slot < nq) {
            int t = s_q[slot];
            mymask = mask4(X[(brow + (size_t)t) * 27 + 16 + li]);
        }
        unsigned bal = __ballot_sync(0xFFFFFFFFu, mymask != 0u);
        unsigned grp = (bal >> (lane & 16)) & 0x7FFu;  // this half-warp's 11 bits
        int fl = __ffs(grp) - 1;                       // first lane-in-group with a hit
        unsigned wmask = __shfl_sync(0xFFFFFFFFu, mymask,
                                     (lane & 16) + (fl < 0 ? 0 : fl));
        if (grp && li == 0 && slot < nq) {
            s_pos[s_q[slot]] = (unsigned short)(64 + 4 * fl + __ffs(wmask) - 1);
        }
    }
    __syncthreads();

    // Coalesced output: block writes its 1792 floats contiguously,
    // reconstructing bits from s_pos (div/mod-7 indexing, ALU is cheap).
    size_t ob = brow * N_OUT;
    size_t total = (size_t)n_rows * N_OUT;
    #pragma unroll
    for (int i = 0; i < N_OUT; ++i) {
        size_t gi = ob + (size_t)(i * TPB + tid);
        if (gi < total) {
            int local = i * TPB + tid;   // 0..1791
            int r = local / N_OUT;
            int b = local - r * N_OUT;
            out[gi] = (float)((s_pos[r] >> (6 - b)) & 1);
        }
    }
}

extern "C" void kernel_launch(void* const* d_in, const int* in_sizes, int n_in,
                              void* d_out, int out_size) {
    const uint4* X = (const uint4*)d_in[0];
    float* out = (float*)d_out;
    int n_rows = in_sizes[0] / N_BITS;

    int blocks = (n_rows + TPB - 1) / TPB;
    lzd108_kernel<<<blocks, TPB>>>(X, out, n_rows);
}

// round 9
// speedup vs baseline: 1.4121x; 1.0003x over previous
#include <cuda_runtime.h>
#include <cstdint>

#define N_BITS 108
#define N_OUT  7
#define TPB    256

// Row = 108 floats = 432 B = 27 uint4. DRAM effective granule = 64 B
// (established R5-R7: aligned-window R6 measured 526 MB vs 565-594 MB for
// row-aligned schedules). Scan each row through a 64B-aligned window:
//   a0 = (27*row) & ~3   (uint4 index), d = 4*((27*row)&3) junk floats.
// Four rounds of 128 B (8 x LDG.128), window floats [0,32) [32,64) [64,96)
// [96,128). Coverage of round 0 is 32-d >= 20 bits, so no coverage collapse
// (R6's failure). All masks 32-bit; only round 3 needs a bounds clamp.
// Values are exactly 0.0f / 1.0f: (word >> 29) & 1 extracts the bit.

__device__ __forceinline__ unsigned mask4(uint4 w) {
    return ((w.x >> 29) & 1u)
         | (((w.y >> 29) & 1u) << 1)
         | (((w.z >> 29) & 1u) << 2)
         | (((w.w >> 29) & 1u) << 3);
}

__global__ __launch_bounds__(TPB, 8)
void lzd108_kernel(const uint4* __restrict__ X, float* __restrict__ out,
                   int n_rows, unsigned lim /* total uint4 count */) {
    __shared__ unsigned short s_pos[TPB];

    int tid = threadIdx.x;
    size_t brow = (size_t)blockIdx.x * TPB;
    int row = (int)brow + tid;
    int pos = N_BITS;  // 108 = 1101100b == LZC_108 (all-zero row)

    if (row < n_rows) {
        unsigned w0 = 27u * (unsigned)row;   // uint4 index of row start
        unsigned a0 = w0 & ~3u;              // 64B-aligned window base
        int d = 4 * (int)(w0 & 3u);          // junk floats at window start
        unsigned last = lim - 1u;
        const uint4* p = X + a0;

        int pw = -1;  // first-one position in WINDOW floats; row pos = pw - d

        // Round 0: window floats [0,32) — aligned 128 B
        unsigned m = 0;
        #pragma unroll
        for (int j = 0; j < 8; ++j) m |= mask4(__ldg(p + j)) << (4 * j);
        m &= 0xFFFFFFFFu << d;               // drop previous-row junk
        if (m) {
            pw = __ffs(m) - 1;
        } else {
            // Round 1: floats [32,64) — aligned 128 B
            m = 0;
            #pragma unroll
            for (int j = 0; j < 8; ++j) m |= mask4(__ldg(p + 8 + j)) << (4 * j);
            if (m) {
                pw = 32 + __ffs(m) - 1;
            } else {
                // Round 2: floats [64,96) — aligned 128 B
                m = 0;
                #pragma unroll
                for (int j = 0; j < 8; ++j) m |= mask4(__ldg(p + 16 + j)) << (4 * j);
                if (m) {
                    pw = 64 + __ffs(m) - 1;
                } else {
                    // Round 3: floats [96,128) — aligned 128 B, clamped at end.
                    // Valid row floats: window float < 108 + d -> bit < 12 + d;
                    // clamped duplicate words fall outside that mask.
                    m = 0;
                    #pragma unroll
                    for (int j = 0; j < 8; ++j) {
                        unsigned gi = a0 + 24 + j;
                        uint4 w = __ldg(X + min(gi, last));
                        m |= mask4(w) << (4 * j);
                    }
                    m &= (1u << (12 + d)) - 1u;
                    if (m) pw = 96 + __ffs(m) - 1;
                }
            }
        }
        if (pw >= 0) pos = pw - d;
    }

    s_pos[tid] = (unsigned short)pos;
    __syncthreads();

    // Coalesced output: block writes its 1792 floats contiguously,
    // reconstructing bits from s_pos.
    size_t ob = brow * N_OUT;
    size_t total = (size_t)n_rows * N_OUT;
    #pragma unroll
    for (int i = 0; i < N_OUT; ++i) {
        size_t gi = ob + (size_t)(i * TPB + tid);
        if (gi < total) {
            int local = i * TPB + tid;   // 0..1791
            int r = local / N_OUT;
            int b = local - r * N_OUT;
            out[gi] = (float)((s_pos[r] >> (6 - b)) & 1);
        }
    }
}

extern "C" void kernel_launch(void* const* d_in, const int* in_sizes, int n_in,
                              void* d_out, int out_size) {
    const uint4* X = (const uint4*)d_in[0];
    float* out = (float*)d_out;
    int n_rows = in_sizes[0] / N_BITS;
    unsigned lim = (unsigned)(in_sizes[0] / 4);  // total uint4 count

    int blocks = (n_rows + TPB - 1) / TPB;
    lzd108_kernel<<<blocks, TPB>>>(X, out, n_rows, lim);
}